// round 3
// baseline (speedup 1.0000x reference)
#include <cuda_runtime.h>
#include <cstdint>

// Geometry (fixed by dataset): B=32, C=3, H=W=512
#define HW4_SHIFT 16
#define HW4       (1 << HW4_SHIFT)            // 65536 float4-groups per plane
#define NPIX      (32LL * 512 * 512)          // 8,388,608 pixels

#define THREADS   256
#define NBLOCKS   8192                        // NBLOCKS*THREADS == 2,097,152 groups

__device__ float        g_partials[NBLOCKS];
__device__ unsigned int g_ticket;             // zero-init, reset by last block

__device__ __forceinline__ float hue1(float r, float g, float b) {
    float maxc = fmaxf(r, fmaxf(g, b));
    float minc = fminf(r, fminf(g, b));
    float delta = maxc - minc;
    float inv   = 1.0f / ((delta == 0.0f) ? 1.0f : delta);
    float h;
    if (maxc == r)      h = (g - b) * inv;
    else if (maxc == g) h = 2.0f + (b - r) * inv;
    else                h = 4.0f + (r - g) * inv;
    h = (delta == 0.0f) ? 0.0f : h * (1.0f / 6.0f);
    return h - floorf(h);                     // h/6 mod 1.0 (jnp semantics)
}

__device__ __forceinline__ float pix_loss(float hp, float ht) {
    float d = fabsf(hp - ht);
    return (d < 0.5f) ? d : (d - 0.5f);       // d==0.5 contributes 0 either way
}

__global__ __launch_bounds__(THREADS)
void hsv_loss_fused(const float4* __restrict__ pred,
                    const float4* __restrict__ targ,
                    float* __restrict__ out) {
    int gid = blockIdx.x * THREADS + threadIdx.x;   // one float4 group per thread
    int b   = gid >> HW4_SHIFT;
    int p4  = gid & (HW4 - 1);
    long long base = ((long long)b * 3) * HW4 + p4;

    // 6 independent LDG.128, front-batched (no loop carry -> full MLP)
    float4 pr = __ldcs(&pred[base]);
    float4 pg = __ldcs(&pred[base + HW4]);
    float4 pb = __ldcs(&pred[base + 2 * HW4]);
    float4 tr = __ldcs(&targ[base]);
    float4 tg = __ldcs(&targ[base + HW4]);
    float4 tb = __ldcs(&targ[base + 2 * HW4]);

    float acc;
    acc  = pix_loss(hue1(pr.x, pg.x, pb.x), hue1(tr.x, tg.x, tb.x));
    acc += pix_loss(hue1(pr.y, pg.y, pb.y), hue1(tr.y, tg.y, tb.y));
    acc += pix_loss(hue1(pr.z, pg.z, pb.z), hue1(tr.z, tg.z, tb.z));
    acc += pix_loss(hue1(pr.w, pg.w, pb.w), hue1(tr.w, tg.w, tb.w));

    // ---- block reduce ----
    #pragma unroll
    for (int off = 16; off > 0; off >>= 1)
        acc += __shfl_xor_sync(0xFFFFFFFFu, acc, off);

    __shared__ float swarp[THREADS / 32];
    int lane = threadIdx.x & 31;
    int wid  = threadIdx.x >> 5;
    if (lane == 0) swarp[wid] = acc;
    __syncthreads();

    __shared__ bool isLast;
    if (threadIdx.x == 0) {
        float v = 0.0f;
        #pragma unroll
        for (int w = 0; w < THREADS / 32; w++) v += swarp[w];
        g_partials[blockIdx.x] = v;
        __threadfence();
        unsigned int t = atomicAdd(&g_ticket, 1u);
        isLast = (t == NBLOCKS - 1);
    }
    __syncthreads();

    // ---- last block finishes: 8192 partials, 32/thread, 4 indep accumulators ----
    if (isLast) {
        double a0 = 0.0, a1 = 0.0, a2 = 0.0, a3 = 0.0;
        #pragma unroll
        for (int k = 0; k < NBLOCKS / THREADS; k += 4) {
            a0 += (double)g_partials[(k + 0) * THREADS + threadIdx.x];
            a1 += (double)g_partials[(k + 1) * THREADS + threadIdx.x];
            a2 += (double)g_partials[(k + 2) * THREADS + threadIdx.x];
            a3 += (double)g_partials[(k + 3) * THREADS + threadIdx.x];
        }
        double dacc = (a0 + a1) + (a2 + a3);

        #pragma unroll
        for (int off = 16; off > 0; off >>= 1)
            dacc += __shfl_xor_sync(0xFFFFFFFFu, dacc, off);

        __shared__ double sd[THREADS / 32];
        if (lane == 0) sd[wid] = dacc;
        __syncthreads();
        if (threadIdx.x == 0) {
            double v = 0.0;
            #pragma unroll
            for (int w = 0; w < THREADS / 32; w++) v += sd[w];
            out[0] = (float)(v / (double)NPIX);
            g_ticket = 0;                     // reset for next graph replay
        }
    }
}

extern "C" void kernel_launch(void* const* d_in, const int* in_sizes, int n_in,
                              void* d_out, int out_size) {
    const float4* pred = (const float4*)d_in[0];
    const float4* targ = (const float4*)d_in[1];
    float* out = (float*)d_out;
    hsv_loss_fused<<<NBLOCKS, THREADS>>>(pred, targ, out);
}

// round 4
// speedup vs baseline: 1.0514x; 1.0514x over previous
#include <cuda_runtime.h>
#include <cstdint>

// Geometry (fixed by dataset): B=32, C=3, H=W=512
#define HW4_SHIFT 16
#define HW4       (1 << HW4_SHIFT)            // 65536 float4-groups per plane
#define NPIX      (32LL * 512 * 512)          // 8,388,608 pixels

#define THREADS   256
#define NBLOCKS   2048
#define ITERS     4                           // NBLOCKS*THREADS*ITERS == 2,097,152 groups

__device__ float        g_partials[NBLOCKS];
__device__ unsigned int g_ticket;             // zero-init, reset by last block

// Hue in SIX-units: returns 6*h where h = (hue/6 mod 1). Range [0,6).
__device__ __forceinline__ float hue6(float r, float g, float b) {
    float maxc  = fmaxf(r, fmaxf(g, b));
    float minc  = fminf(r, fminf(g, b));
    float delta = maxc - minc;
    bool  zero  = (delta == 0.0f);
    float safe  = zero ? 1.0f : delta;
    float inv;
    asm("rcp.approx.f32 %0, %1;" : "=f"(inv) : "f"(safe));

    float cr = (g - b) * inv;                 // [-1, 1]
    float cg = fmaf(b - r, inv, 2.0f);        // [ 1, 3]
    float cb = fmaf(r - g, inv, 4.0f);        // [ 3, 5]

    float h = (maxc == r) ? cr : ((maxc == g) ? cg : cb);
    h = zero ? 0.0f : h;
    h = (h < 0.0f) ? h + 6.0f : h;            // mod 6 (only first case can be negative)
    return h;
}

// Contribution in six-units: ref is d/6 if d6<3 else (d6-3)/6; factor 1/6 deferred.
__device__ __forceinline__ float pix_loss6(float hp6, float ht6) {
    float d6 = fabsf(hp6 - ht6);
    return (d6 < 3.0f) ? d6 : (d6 - 3.0f);    // d6==3 contributes 0 either way
}

__global__ __launch_bounds__(THREADS)
void hsv_loss_fused(const float4* __restrict__ pred,
                    const float4* __restrict__ targ,
                    float* __restrict__ out) {
    float acc = 0.0f;

    #pragma unroll
    for (int k = 0; k < ITERS; k++) {
        int gid = (k * NBLOCKS + blockIdx.x) * THREADS + threadIdx.x;
        int b   = gid >> HW4_SHIFT;
        int p4  = gid & (HW4 - 1);
        long long base = ((long long)b * 3) * HW4 + p4;

        float4 pr = pred[base];
        float4 pg = pred[base + HW4];
        float4 pb = pred[base + 2 * HW4];
        float4 tr = targ[base];
        float4 tg = targ[base + HW4];
        float4 tb = targ[base + 2 * HW4];

        acc += pix_loss6(hue6(pr.x, pg.x, pb.x), hue6(tr.x, tg.x, tb.x));
        acc += pix_loss6(hue6(pr.y, pg.y, pb.y), hue6(tr.y, tg.y, tb.y));
        acc += pix_loss6(hue6(pr.z, pg.z, pb.z), hue6(tr.z, tg.z, tb.z));
        acc += pix_loss6(hue6(pr.w, pg.w, pb.w), hue6(tr.w, tg.w, tb.w));
    }

    // ---- block reduce ----
    #pragma unroll
    for (int off = 16; off > 0; off >>= 1)
        acc += __shfl_xor_sync(0xFFFFFFFFu, acc, off);

    __shared__ float swarp[THREADS / 32];
    int lane = threadIdx.x & 31;
    int wid  = threadIdx.x >> 5;
    if (lane == 0) swarp[wid] = acc;
    __syncthreads();

    __shared__ bool isLast;
    if (threadIdx.x == 0) {
        float v = 0.0f;
        #pragma unroll
        for (int w = 0; w < THREADS / 32; w++) v += swarp[w];
        g_partials[blockIdx.x] = v;
        __threadfence();
        unsigned int t = atomicAdd(&g_ticket, 1u);
        isLast = (t == NBLOCKS - 1);
    }
    __syncthreads();

    // ---- last block finishes: 2048 partials, 8/thread, indep accumulators ----
    if (isLast) {
        double a0 = 0.0, a1 = 0.0, a2 = 0.0, a3 = 0.0;
        #pragma unroll
        for (int k = 0; k < NBLOCKS / THREADS; k += 4) {
            a0 += (double)g_partials[(k + 0) * THREADS + threadIdx.x];
            a1 += (double)g_partials[(k + 1) * THREADS + threadIdx.x];
            a2 += (double)g_partials[(k + 2) * THREADS + threadIdx.x];
            a3 += (double)g_partials[(k + 3) * THREADS + threadIdx.x];
        }
        double dacc = (a0 + a1) + (a2 + a3);

        #pragma unroll
        for (int off = 16; off > 0; off >>= 1)
            dacc += __shfl_xor_sync(0xFFFFFFFFu, dacc, off);

        __shared__ double sd[THREADS / 32];
        if (lane == 0) sd[wid] = dacc;
        __syncthreads();
        if (threadIdx.x == 0) {
            double v = 0.0;
            #pragma unroll
            for (int w = 0; w < THREADS / 32; w++) v += sd[w];
            out[0] = (float)(v / (6.0 * (double)NPIX));   // deferred 1/6 here
            g_ticket = 0;                                 // reset for next replay
        }
    }
}

extern "C" void kernel_launch(void* const* d_in, const int* in_sizes, int n_in,
                              void* d_out, int out_size) {
    const float4* pred = (const float4*)d_in[0];
    const float4* targ = (const float4*)d_in[1];
    float* out = (float*)d_out;
    hsv_loss_fused<<<NBLOCKS, THREADS>>>(pred, targ, out);
}

// round 5
// speedup vs baseline: 1.1650x; 1.1080x over previous
#include <cuda_runtime.h>
#include <cstdint>

// Geometry (fixed by dataset): B=32, C=3, H=W=512
#define HW4_SHIFT 16
#define HW4       (1 << HW4_SHIFT)            // 65536 float4-groups per plane
#define NPIX      (32LL * 512 * 512)          // 8,388,608 pixels

#define THREADS   256
#define NBLOCKS   8192                        // 1 float4-group per thread

__device__ float4       g_partials4[NBLOCKS / 4];   // viewed as float[NBLOCKS]
__device__ unsigned int g_ticket;                    // zero-init, reset by last block

__device__ __forceinline__ unsigned int ticket_acq_rel(unsigned int* p) {
    unsigned int old;
    asm volatile("atom.acq_rel.gpu.global.add.u32 %0, [%1], 1;"
                 : "=r"(old) : "l"(p) : "memory");
    return old;
}

// Hue in SIX-units: returns 6*h where h = (hue/6 mod 1). Range [0,6).
__device__ __forceinline__ float hue6(float r, float g, float b) {
    float maxc  = fmaxf(r, fmaxf(g, b));
    float minc  = fminf(r, fminf(g, b));
    float delta = maxc - minc;
    float safe  = (delta == 0.0f) ? 1.0f : delta;
    float inv;
    asm("rcp.approx.f32 %0, %1;" : "=f"(inv) : "f"(safe));

    float cr = (g - b) * inv;                 // [-1, 1]; ==0 when delta==0 (safe=1)
    float cg = fmaf(b - r, inv, 2.0f);        // [ 1, 3]
    float cb = fmaf(r - g, inv, 4.0f);        // [ 3, 5]

    // delta==0 -> maxc==r -> picks cr==0: matches reference's h=0 case for free.
    float h = (maxc == r) ? cr : ((maxc == g) ? cg : cb);
    return (h < 0.0f) ? h + 6.0f : h;         // mod 6 (only cr can be negative)
}

// Contribution in six-units; global 1/6 factor deferred to the final divide.
__device__ __forceinline__ float pix_loss6(float hp6, float ht6) {
    float d6 = fabsf(hp6 - ht6);
    return (d6 < 3.0f) ? d6 : (d6 - 3.0f);    // d6==3 contributes 0 either way
}

__global__ __launch_bounds__(THREADS)
void hsv_loss_fused(const float4* __restrict__ pred,
                    const float4* __restrict__ targ,
                    float* __restrict__ out) {
    int gid = blockIdx.x * THREADS + threadIdx.x;   // one float4 group per thread
    int b   = gid >> HW4_SHIFT;
    int p4  = gid & (HW4 - 1);
    long long base = ((long long)b * 3) * HW4 + p4;

    // 6 independent LDG.128, front-batched
    float4 pr = pred[base];
    float4 pg = pred[base + HW4];
    float4 pb = pred[base + 2 * HW4];
    float4 tr = targ[base];
    float4 tg = targ[base + HW4];
    float4 tb = targ[base + 2 * HW4];

    float acc;
    acc  = pix_loss6(hue6(pr.x, pg.x, pb.x), hue6(tr.x, tg.x, tb.x));
    acc += pix_loss6(hue6(pr.y, pg.y, pb.y), hue6(tr.y, tg.y, tb.y));
    acc += pix_loss6(hue6(pr.z, pg.z, pb.z), hue6(tr.z, tg.z, tb.z));
    acc += pix_loss6(hue6(pr.w, pg.w, pb.w), hue6(tr.w, tg.w, tb.w));

    // ---- block reduce ----
    #pragma unroll
    for (int off = 16; off > 0; off >>= 1)
        acc += __shfl_xor_sync(0xFFFFFFFFu, acc, off);

    __shared__ float swarp[THREADS / 32];
    int lane = threadIdx.x & 31;
    int wid  = threadIdx.x >> 5;
    if (lane == 0) swarp[wid] = acc;
    __syncthreads();

    __shared__ bool isLast;
    if (threadIdx.x == 0) {
        float v = 0.0f;
        #pragma unroll
        for (int w = 0; w < THREADS / 32; w++) v += swarp[w];
        ((float*)g_partials4)[blockIdx.x] = v;          // write-through to L2
        // release on the ticket orders the partial store before the increment;
        // acquire lets the winner observe all released partials. NO CCTL.IVALL.
        unsigned int t = ticket_acq_rel(&g_ticket);
        isLast = (t == NBLOCKS - 1);
    }
    __syncthreads();

    // ---- last block: reduce 8192 partials with L1-bypassing float4 loads ----
    if (isLast) {
        double dacc = 0.0;
        #pragma unroll
        for (int k = 0; k < NBLOCKS / 4 / THREADS; k++) {        // 8 indep LDG.128.cv
            float4 v = __ldcv(&g_partials4[k * THREADS + threadIdx.x]);
            dacc += (double)((v.x + v.y) + (v.z + v.w));
        }

        #pragma unroll
        for (int off = 16; off > 0; off >>= 1)
            dacc += __shfl_xor_sync(0xFFFFFFFFu, dacc, off);

        __shared__ double sd[THREADS / 32];
        if (lane == 0) sd[wid] = dacc;
        __syncthreads();
        if (threadIdx.x == 0) {
            double v = 0.0;
            #pragma unroll
            for (int w = 0; w < THREADS / 32; w++) v += sd[w];
            out[0] = (float)(v / (6.0 * (double)NPIX));   // deferred 1/6
            g_ticket = 0;                                 // reset for next replay
        }
    }
}

extern "C" void kernel_launch(void* const* d_in, const int* in_sizes, int n_in,
                              void* d_out, int out_size) {
    const float4* pred = (const float4*)d_in[0];
    const float4* targ = (const float4*)d_in[1];
    float* out = (float*)d_out;
    hsv_loss_fused<<<NBLOCKS, THREADS>>>(pred, targ, out);
}